// round 16
// baseline (speedup 1.0000x reference)
#include <cuda_runtime.h>
#include <cuda_bf16.h>

#define HEADS 4
#define DHEAD 32
#define HID 128
#define CIN 64
#define NPOS 4096
#define NSPLIT 8
#define CHUNK (NPOS / NSPLIT) /* 512 */
#define KT 64                 /* keys per smem tile */
#define NTILES (CHUNK / KT)   /* 8 */
#define L2E 1.4426950408889634f
#define OPAD 40               /* sO row pitch (words); conflict-free quads */
#define WP2 36                /* qkv smem weight pitch v2 (floats) */

typedef unsigned int uint32;

// ---- device scratch ----
__device__ __align__(16) __nv_bfloat16 g_qtb[HEADS * NPOS * DHEAD]; // [h][n][d], scaled
__device__ __align__(16) __nv_bfloat16 g_ktb[HEADS * NPOS * DHEAD]; // [h][n][d]
__device__ __align__(16) __nv_bfloat16 g_vtb[HEADS * DHEAD * NPOS]; // [h][d][n]
__device__ float g_pm[HEADS * NPOS * NSPLIT];
__device__ float g_pl[HEADS * NPOS * NSPLIT];
__device__ __align__(16) float g_pacc[HEADS * NPOS * NSPLIT * DHEAD];

// m16n8k16 bf16 MMA, fp32 accum, D==C in-place
__device__ __forceinline__ void mma16816(float* d, const uint32* a, uint32 b0, uint32 b1)
{
    asm volatile(
        "mma.sync.aligned.m16n8k16.row.col.f32.bf16.bf16.f32 "
        "{%0,%1,%2,%3},{%4,%5,%6,%7},{%8,%9},{%0,%1,%2,%3};"
        : "+f"(d[0]), "+f"(d[1]), "+f"(d[2]), "+f"(d[3])
        : "r"(a[0]), "r"(a[1]), "r"(a[2]), "r"(a[3]), "r"(b0), "r"(b1));
}

// m16n8k8 tf32 MMA, fp32 accum, D==C in-place
__device__ __forceinline__ void mma1688_tf32(float* d, const uint32* a, uint32 b0, uint32 b1)
{
    asm volatile(
        "mma.sync.aligned.m16n8k8.row.col.f32.tf32.tf32.f32 "
        "{%0,%1,%2,%3},{%4,%5,%6,%7},{%8,%9},{%0,%1,%2,%3};"
        : "+f"(d[0]), "+f"(d[1]), "+f"(d[2]), "+f"(d[3])
        : "r"(a[0]), "r"(a[1]), "r"(a[2]), "r"(a[3]), "r"(b0), "r"(b1));
}

__device__ __forceinline__ uint32 to_tf32(float f)
{
    uint32 r;
    asm("cvt.rna.tf32.f32 %0, %1;" : "=r"(r) : "f"(f));
    return r;
}

__device__ __forceinline__ float ex2(float x)
{
    float y;
    asm("ex2.approx.f32 %0, %1;" : "=f"(y) : "f"(x));
    return y;
}

__device__ __forceinline__ uint32 pk2(float lo, float hi)
{
    __nv_bfloat162 t = __floats2bfloat162_rn(lo, hi);
    return *(uint32*)&t;
}

// ============================================================
// Kernel 1: QKV GEMM v2. Block = 8 o-groups x 32 n-lanes; thread 4o x 4n.
// Block covers 128 n x 32 o (one segment+head slice). Grid (32, 12).
// Per c: 1 LDG.128 (x) + 1 warp-uniform LDS.128 (w) + 16 FFMA.
// ============================================================
__global__ void __launch_bounds__(256) qkv_kernel(
    const float* __restrict__ x, const float* __restrict__ w)
{
    __shared__ float ws[CIN * WP2];   // [c][32 o], pitch 36 -> 9.2 KB

    int tid = threadIdx.x;
    int o0 = blockIdx.y * 32;

    // stage weights transposed: ws[c][oo] = w[o0+oo][c]
    for (int idx = tid; idx < 32 * CIN; idx += 256) {
        int oo = idx >> 6, c = idx & 63;
        ws[c * WP2 + oo] = w[(size_t)(o0 + oo) * CIN + c];
    }
    __syncthreads();

    int nt = tid & 31;            // n-lane
    int ot = tid >> 5;            // o-group 0..7 (4 o each)
    int n = blockIdx.x * 128 + nt * 4;

    float acc[4][4];
#pragma unroll
    for (int k = 0; k < 4; k++)
#pragma unroll
        for (int j = 0; j < 4; j++) acc[k][j] = 0.f;

#pragma unroll 8
    for (int c = 0; c < CIN; c++) {
        float4 xv = *(const float4*)(x + (size_t)c * NPOS + n);
        float4 wv = *(const float4*)(ws + c * WP2 + ot * 4);
        acc[0][0] += wv.x * xv.x; acc[0][1] += wv.x * xv.y;
        acc[0][2] += wv.x * xv.z; acc[0][3] += wv.x * xv.w;
        acc[1][0] += wv.y * xv.x; acc[1][1] += wv.y * xv.y;
        acc[1][2] += wv.y * xv.z; acc[1][3] += wv.y * xv.w;
        acc[2][0] += wv.z * xv.x; acc[2][1] += wv.z * xv.y;
        acc[2][2] += wv.z * xv.z; acc[2][3] += wv.z * xv.w;
        acc[3][0] += wv.w * xv.x; acc[3][1] += wv.w * xv.y;
        acc[3][2] += wv.w * xv.z; acc[3][3] += wv.w * xv.w;
    }

    int seg = o0 >> 7;            // uniform per block
    int h = (o0 & 127) >> 5;      // uniform per block
    int d0 = ot * 4;              // d offset of this thread's 4 o's

    if (seg < 2) {
        float scale = (seg == 0) ? 0.17677669529663687f : 1.f;
        __nv_bfloat16* base = (seg == 0 ? g_qtb : g_ktb);
#pragma unroll
        for (int j = 0; j < 4; j++) {
            uint2 pk;
            pk.x = pk2(acc[0][j] * scale, acc[1][j] * scale);
            pk.y = pk2(acc[2][j] * scale, acc[3][j] * scale);
            *(uint2*)(base + (size_t)(h * NPOS + n + j) * DHEAD + d0) = pk;
        }
    } else {
#pragma unroll
        for (int k = 0; k < 4; k++) {
            uint2 pk;
            pk.x = pk2(acc[k][0], acc[k][1]);
            pk.y = pk2(acc[k][2], acc[k][3]);
            *(uint2*)(g_vtb + (size_t)(h * DHEAD + d0 + k) * NPOS + n) = pk;
        }
    }
}

// ============================================================
// Kernel 2: tensor-core flash attention, batched softmax, K/V prefetch.
// grid 1024: bx = h(4) x split(8) x qblk(32). 8 warps x 16 queries.
// ============================================================
__global__ void __launch_bounds__(256) flash_kernel()
{
    __shared__ __nv_bfloat16 sK[KT * 40];      // [64 keys][32 d], rows padded to 80B
    __shared__ __nv_bfloat16 sVt[DHEAD * 72];  // [32 d][64 keys], rows padded to 144B
    uint32* sKu = (uint32*)sK;
    uint32* sVu = (uint32*)sVt;

    int bx = blockIdx.x;
    int qblk = bx & 31, split = (bx >> 5) & 7, h = bx >> 8;
    int tid = threadIdx.x, w = tid >> 5, lane = tid & 31;
    int g = lane >> 2, tg = lane & 3;
    int q0 = qblk * 128 + w * 16;

    uint32 qa[2][4];
    {
        const uint32* Qb = (const uint32*)g_qtb + (size_t)(h * NPOS + q0) * 16;
#pragma unroll
        for (int ks = 0; ks < 2; ks++) {
            qa[ks][0] = Qb[g * 16 + tg + 8 * ks];
            qa[ks][1] = Qb[(g + 8) * 16 + tg + 8 * ks];
            qa[ks][2] = Qb[g * 16 + tg + 4 + 8 * ks];
            qa[ks][3] = Qb[(g + 8) * 16 + tg + 4 + 8 * ks];
        }
    }

    float o[4][4];
#pragma unroll
    for (int a = 0; a < 4; a++)
#pragma unroll
        for (int b = 0; b < 4; b++) o[a][b] = 0.f;
    float m0 = -1e30f, m1 = -1e30f, l0 = 0.f, l1 = 0.f;

    const uint32* Kg = (const uint32*)g_ktb + (size_t)(h * NPOS + split * CHUNK) * 16;
    const uint32* Vg = (const uint32*)g_vtb + (size_t)(h * DHEAD) * (NPOS / 2) + split * (CHUNK / 2);

    int krow_st[4], kcol_st[4], vrow_st[4], vcol_st[4];
#pragma unroll
    for (int it = 0; it < 4; it++) {
        int idx = tid + it * 256;
        krow_st[it] = idx >> 4; kcol_st[it] = idx & 15;
        vrow_st[it] = idx >> 5; vcol_st[it] = idx & 31;
    }

    uint32 pkf[4], pvf[4];
#pragma unroll
    for (int it = 0; it < 4; it++) {
        pkf[it] = Kg[(size_t)krow_st[it] * 16 + kcol_st[it]];
        pvf[it] = Vg[(size_t)vrow_st[it] * (NPOS / 2) + vcol_st[it]];
    }

    for (int tile = 0; tile < NTILES; tile++) {
        __syncthreads();
#pragma unroll
        for (int it = 0; it < 4; it++) {
            sKu[krow_st[it] * 20 + kcol_st[it]] = pkf[it];
            sVu[vrow_st[it] * 36 + vcol_st[it]] = pvf[it];
        }
        __syncthreads();

        if (tile + 1 < NTILES) {
#pragma unroll
            for (int it = 0; it < 4; it++) {
                pkf[it] = Kg[(size_t)((tile + 1) * 64 + krow_st[it]) * 16 + kcol_st[it]];
                pvf[it] = Vg[(size_t)vrow_st[it] * (NPOS / 2) + (tile + 1) * 32 + vcol_st[it]];
            }
        }

        // ---- Phase 1: S MMAs ----
        float sS[4][2][4];
#pragma unroll
        for (int kt = 0; kt < 4; kt++) {
#pragma unroll
            for (int nt = 0; nt < 2; nt++)
#pragma unroll
                for (int c = 0; c < 4; c++) sS[kt][nt][c] = 0.f;
#pragma unroll
            for (int ks = 0; ks < 2; ks++) {
#pragma unroll
                for (int nt = 0; nt < 2; nt++) {
                    int krow = kt * 16 + nt * 8 + g;
                    uint32 b0 = sKu[krow * 20 + tg + 8 * ks];
                    uint32 b1 = sKu[krow * 20 + tg + 4 + 8 * ks];
                    mma16816(sS[kt][nt], qa[ks], b0, b1);
                }
            }
        }

        // ---- Phase 2: one softmax pass ----
        float tm0 = -1e30f, tm1 = -1e30f;
#pragma unroll
        for (int kt = 0; kt < 4; kt++) {
#pragma unroll
            for (int nt = 0; nt < 2; nt++) {
                tm0 = fmaxf(tm0, fmaxf(sS[kt][nt][0], sS[kt][nt][1]));
                tm1 = fmaxf(tm1, fmaxf(sS[kt][nt][2], sS[kt][nt][3]));
            }
        }
        tm0 = fmaxf(tm0, __shfl_xor_sync(0xffffffffu, tm0, 1));
        tm0 = fmaxf(tm0, __shfl_xor_sync(0xffffffffu, tm0, 2));
        tm1 = fmaxf(tm1, __shfl_xor_sync(0xffffffffu, tm1, 1));
        tm1 = fmaxf(tm1, __shfl_xor_sync(0xffffffffu, tm1, 2));
        float nm0 = fmaxf(m0, tm0), nm1 = fmaxf(m1, tm1);
        float c0 = ex2((m0 - nm0) * L2E);
        float c1 = ex2((m1 - nm1) * L2E);
        m0 = nm0; m1 = nm1;
        l0 *= c0; l1 *= c1;
#pragma unroll
        for (int nt = 0; nt < 4; nt++) {
            o[nt][0] *= c0; o[nt][1] *= c0;
            o[nt][2] *= c1; o[nt][3] *= c1;
        }

        // ---- Phase 3: exp + PV MMAs ----
#pragma unroll
        for (int kt = 0; kt < 4; kt++) {
            float p00 = ex2((sS[kt][0][0] - nm0) * L2E);
            float p01 = ex2((sS[kt][0][1] - nm0) * L2E);
            float p10 = ex2((sS[kt][1][0] - nm0) * L2E);
            float p11 = ex2((sS[kt][1][1] - nm0) * L2E);
            float p02 = ex2((sS[kt][0][2] - nm1) * L2E);
            float p03 = ex2((sS[kt][0][3] - nm1) * L2E);
            float p12 = ex2((sS[kt][1][2] - nm1) * L2E);
            float p13 = ex2((sS[kt][1][3] - nm1) * L2E);

            l0 += (p00 + p01) + (p10 + p11);
            l1 += (p02 + p03) + (p12 + p13);

            uint32 pa[4];
            pa[0] = pk2(p00, p01);
            pa[1] = pk2(p02, p03);
            pa[2] = pk2(p10, p11);
            pa[3] = pk2(p12, p13);

#pragma unroll
            for (int nt = 0; nt < 4; nt++) {
                int vrow = nt * 8 + g;
                uint32 b0 = sVu[vrow * 36 + kt * 8 + tg];
                uint32 b1 = sVu[vrow * 36 + kt * 8 + tg + 4];
                mma16816(o[nt], pa, b0, b1);
            }
        }
    }

    l0 += __shfl_xor_sync(0xffffffffu, l0, 1);
    l0 += __shfl_xor_sync(0xffffffffu, l0, 2);
    l1 += __shfl_xor_sync(0xffffffffu, l1, 1);
    l1 += __shfl_xor_sync(0xffffffffu, l1, 2);

    int qg0 = h * NPOS + q0 + g;
    int qg1 = qg0 + 8;
    int pi0 = qg0 * NSPLIT + split;
    int pi1 = qg1 * NSPLIT + split;
    g_pm[pi0] = m0; g_pl[pi0] = l0;
    g_pm[pi1] = m1; g_pl[pi1] = l1;

    float2* P0 = (float2*)(g_pacc + (size_t)pi0 * 32);
    float2* P1 = (float2*)(g_pacc + (size_t)pi1 * 32);
#pragma unroll
    for (int nt = 0; nt < 4; nt++) {
        P0[nt * 4 + tg] = make_float2(o[nt][0], o[nt][1]);
        P1[nt * 4 + tg] = make_float2(o[nt][2], o[nt][3]);
    }
}

// ============================================================
// Kernel 3 (FUSED reduce + outproj): block owns 16 n-positions.
// ============================================================
__global__ void __launch_bounds__(256) fused_out_kernel(
    const float* __restrict__ w, const float* __restrict__ b, float* __restrict__ y)
{
    __shared__ float sO[HID * OPAD];
    int tid = threadIdx.x;
    int n0 = blockIdx.x * 16;

    // ---- Phase A: 64 (h,i) pairs, 4 threads each (8 d's per thread) ----
    {
        int pair = tid >> 2;
        int hh = pair >> 4;
        int il = pair & 15;
        int dq = (tid & 3) * 8;
        int i = n0 + il;
        int base = (hh * NPOS + i) * NSPLIT;

        float pm[NSPLIT], pl[NSPLIT];
#pragma unroll
        for (int s = 0; s < NSPLIT; s++) { pm[s] = g_pm[base + s]; pl[s] = g_pl[base + s]; }
        float M = pm[0];
#pragma unroll
        for (int s = 1; s < NSPLIT; s++) M = fmaxf(M, pm[s]);

        float L = 0.f;
        float num[8];
#pragma unroll
        for (int d = 0; d < 8; d++) num[d] = 0.f;

#pragma unroll
        for (int s = 0; s < NSPLIT; s++) {
            float es = ex2((pm[s] - M) * L2E);
            L += pl[s] * es;
            const float4* pa = (const float4*)(g_pacc + (size_t)(base + s) * 32 + dq);
            float4 a0 = pa[0], a1 = pa[1];
            num[0] += a0.x * es; num[1] += a0.y * es;
            num[2] += a0.z * es; num[3] += a0.w * es;
            num[4] += a1.x * es; num[5] += a1.y * es;
            num[6] += a1.z * es; num[7] += a1.w * es;
        }
        float inv = 1.f / L;
#pragma unroll
        for (int d = 0; d < 8; d++)
            sO[(hh * DHEAD + dq + d) * OPAD + il] = num[d] * inv;
    }
    __syncthreads();

    // ---- Phase B: tf32 MMA ----
    int wp = tid >> 5, lane = tid & 31;
    int g = lane >> 2, tg = lane & 3;
    int ow = wp & 3, nw = wp >> 2;
    int o0 = ow * 16;
    int nl0 = nw * 8;

    float c[4] = {0.f, 0.f, 0.f, 0.f};
    const float* wA0 = w + (size_t)(o0 + g) * HID;
    const float* wA1 = w + (size_t)(o0 + g + 8) * HID;

#pragma unroll
    for (int ks = 0; ks < 16; ks++) {
        int k0 = ks * 8;
        uint32 a[4];
        a[0] = to_tf32(wA0[k0 + tg]);
        a[1] = to_tf32(wA1[k0 + tg]);
        a[2] = to_tf32(wA0[k0 + tg + 4]);
        a[3] = to_tf32(wA1[k0 + tg + 4]);

        uint32 b0 = to_tf32(sO[(k0 + tg) * OPAD + nl0 + g]);
        uint32 b1 = to_tf32(sO[(k0 + tg + 4) * OPAD + nl0 + g]);
        mma1688_tf32(c, a, b0, b1);
    }

    float bb0 = b[o0 + g];
    float bb1 = b[o0 + g + 8];
    int n = n0 + nl0;
    *(float2*)(y + (size_t)(o0 + g) * NPOS + n + 2 * tg)     = make_float2(c[0] + bb0, c[1] + bb0);
    *(float2*)(y + (size_t)(o0 + g + 8) * NPOS + n + 2 * tg) = make_float2(c[2] + bb1, c[3] + bb1);
}

// ============================================================
extern "C" void kernel_launch(void* const* d_in, const int* in_sizes, int n_in,
                              void* d_out, int out_size)
{
    const float* x     = (const float*)d_in[0];
    const float* w_qkv = (const float*)d_in[1];
    const float* w_out = (const float*)d_in[2];
    const float* b_out = (const float*)d_in[3];
    float* y = (float*)d_out;

    qkv_kernel<<<dim3(32, 12), 256>>>(x, w_qkv);
    flash_kernel<<<1024, 256>>>();
    fused_out_kernel<<<256, 256>>>(w_out, b_out, y);
}

// round 17
// speedup vs baseline: 1.0242x; 1.0242x over previous
#include <cuda_runtime.h>
#include <cuda_bf16.h>

#define HEADS 4
#define DHEAD 32
#define HID 128
#define CIN 64
#define NPOS 4096
#define NSPLIT 8
#define CHUNK (NPOS / NSPLIT) /* 512 */
#define KT 64                 /* keys per smem tile */
#define NTILES (CHUNK / KT)   /* 8 */
#define L2E 1.4426950408889634f
#define OPAD 40               /* sO row pitch (words); conflict-free quads */

typedef unsigned int uint32;

// ---- device scratch ----
__device__ __align__(16) __nv_bfloat16 g_qtb[HEADS * NPOS * DHEAD]; // [h][n][d], scaled
__device__ __align__(16) __nv_bfloat16 g_ktb[HEADS * NPOS * DHEAD]; // [h][n][d]
__device__ __align__(16) __nv_bfloat16 g_vtb[HEADS * DHEAD * NPOS]; // [h][d][n]
__device__ float g_pm[HEADS * NPOS * NSPLIT];
__device__ float g_pl[HEADS * NPOS * NSPLIT];
__device__ __align__(16) float g_pacc[HEADS * NPOS * NSPLIT * DHEAD];

// m16n8k16 bf16 MMA, fp32 accum, D==C in-place
__device__ __forceinline__ void mma16816(float* d, const uint32* a, uint32 b0, uint32 b1)
{
    asm volatile(
        "mma.sync.aligned.m16n8k16.row.col.f32.bf16.bf16.f32 "
        "{%0,%1,%2,%3},{%4,%5,%6,%7},{%8,%9},{%0,%1,%2,%3};"
        : "+f"(d[0]), "+f"(d[1]), "+f"(d[2]), "+f"(d[3])
        : "r"(a[0]), "r"(a[1]), "r"(a[2]), "r"(a[3]), "r"(b0), "r"(b1));
}

// m16n8k8 tf32 MMA, fp32 accum, D==C in-place
__device__ __forceinline__ void mma1688_tf32(float* d, const uint32* a, uint32 b0, uint32 b1)
{
    asm volatile(
        "mma.sync.aligned.m16n8k8.row.col.f32.tf32.tf32.f32 "
        "{%0,%1,%2,%3},{%4,%5,%6,%7},{%8,%9},{%0,%1,%2,%3};"
        : "+f"(d[0]), "+f"(d[1]), "+f"(d[2]), "+f"(d[3])
        : "r"(a[0]), "r"(a[1]), "r"(a[2]), "r"(a[3]), "r"(b0), "r"(b1));
}

__device__ __forceinline__ uint32 to_tf32(float f)
{
    uint32 r;
    asm("cvt.rna.tf32.f32 %0, %1;" : "=r"(r) : "f"(f));
    return r;
}

__device__ __forceinline__ float ex2(float x)
{
    float y;
    asm("ex2.approx.f32 %0, %1;" : "=f"(y) : "f"(x));
    return y;
}

__device__ __forceinline__ uint32 pk2(float lo, float hi)
{
    __nv_bfloat162 t = __floats2bfloat162_rn(lo, hi);
    return *(uint32*)&t;
}

// ============================================================
// Kernel 1: QKV GEMM on tensor pipe (tf32 MMA).
// A = w_qkv [384 o][64 c] row-major; B = x [64 c][4096 n] col fragment.
// Grid (128, 3) x 256 threads; warp = 16 o x 32 n; k=64 (8 steps).
// blockIdx.y = segment (0=Q,1=K,2=V); o0 16-aligned, single head per warp.
// ============================================================
__global__ void __launch_bounds__(256) qkv_kernel(
    const float* __restrict__ x, const float* __restrict__ w)
{
    int tid = threadIdx.x, wp = tid >> 5, lane = tid & 31;
    int g = lane >> 2, tg = lane & 3;
    int o0 = blockIdx.y * 128 + wp * 16;
    int n0 = blockIdx.x * 32;

    float c[4][4];
#pragma unroll
    for (int nt = 0; nt < 4; nt++)
#pragma unroll
        for (int j = 0; j < 4; j++) c[nt][j] = 0.f;

    const float* wA0 = w + (size_t)(o0 + g) * CIN;
    const float* wA1 = w + (size_t)(o0 + g + 8) * CIN;

#pragma unroll
    for (int ks = 0; ks < 8; ks++) {
        int k0 = ks * 8;
        uint32 a[4];
        a[0] = to_tf32(wA0[k0 + tg]);
        a[1] = to_tf32(wA1[k0 + tg]);
        a[2] = to_tf32(wA0[k0 + tg + 4]);
        a[3] = to_tf32(wA1[k0 + tg + 4]);

        const float* B0 = x + (size_t)(k0 + tg) * NPOS + n0 + g;
        const float* B1 = x + (size_t)(k0 + tg + 4) * NPOS + n0 + g;
#pragma unroll
        for (int nt = 0; nt < 4; nt++) {
            uint32 b0 = to_tf32(B0[nt * 8]);
            uint32 b1 = to_tf32(B1[nt * 8]);
            mma1688_tf32(c[nt], a, b0, b1);
        }
    }

    int seg = blockIdx.y;         // 0=q 1=k 2=v, uniform
    int os = o0 & 127;
    int h = os >> 5, d0 = os & 31;   // d0 in {0,16}

    if (seg < 2) {
        float scale = (seg == 0) ? 0.17677669529663687f : 1.f;
        __nv_bfloat16* base = (seg == 0 ? g_qtb : g_ktb) + (size_t)h * NPOS * DHEAD;
#pragma unroll
        for (int nt = 0; nt < 4; nt++) {
            int n = n0 + nt * 8 + 2 * tg;
            base[(size_t)n * DHEAD + d0 + g]           = __float2bfloat16(c[nt][0] * scale);
            base[(size_t)(n + 1) * DHEAD + d0 + g]     = __float2bfloat16(c[nt][1] * scale);
            base[(size_t)n * DHEAD + d0 + g + 8]       = __float2bfloat16(c[nt][2] * scale);
            base[(size_t)(n + 1) * DHEAD + d0 + g + 8] = __float2bfloat16(c[nt][3] * scale);
        }
    } else {
        __nv_bfloat16* base = g_vtb + (size_t)h * DHEAD * NPOS;
#pragma unroll
        for (int nt = 0; nt < 4; nt++) {
            int n = n0 + nt * 8 + 2 * tg;
            *(uint32*)(base + (size_t)(d0 + g) * NPOS + n)     = pk2(c[nt][0], c[nt][1]);
            *(uint32*)(base + (size_t)(d0 + g + 8) * NPOS + n) = pk2(c[nt][2], c[nt][3]);
        }
    }
}

// ============================================================
// Kernel 2: tensor-core flash attention, batched softmax, K/V prefetch.
// grid 1024: bx = h(4) x split(8) x qblk(32). 8 warps x 16 queries.
// ============================================================
__global__ void __launch_bounds__(256) flash_kernel()
{
    __shared__ __nv_bfloat16 sK[KT * 40];      // [64 keys][32 d], rows padded to 80B
    __shared__ __nv_bfloat16 sVt[DHEAD * 72];  // [32 d][64 keys], rows padded to 144B
    uint32* sKu = (uint32*)sK;
    uint32* sVu = (uint32*)sVt;

    int bx = blockIdx.x;
    int qblk = bx & 31, split = (bx >> 5) & 7, h = bx >> 8;
    int tid = threadIdx.x, w = tid >> 5, lane = tid & 31;
    int g = lane >> 2, tg = lane & 3;
    int q0 = qblk * 128 + w * 16;

    uint32 qa[2][4];
    {
        const uint32* Qb = (const uint32*)g_qtb + (size_t)(h * NPOS + q0) * 16;
#pragma unroll
        for (int ks = 0; ks < 2; ks++) {
            qa[ks][0] = Qb[g * 16 + tg + 8 * ks];
            qa[ks][1] = Qb[(g + 8) * 16 + tg + 8 * ks];
            qa[ks][2] = Qb[g * 16 + tg + 4 + 8 * ks];
            qa[ks][3] = Qb[(g + 8) * 16 + tg + 4 + 8 * ks];
        }
    }

    float o[4][4];
#pragma unroll
    for (int a = 0; a < 4; a++)
#pragma unroll
        for (int b = 0; b < 4; b++) o[a][b] = 0.f;
    float m0 = -1e30f, m1 = -1e30f, l0 = 0.f, l1 = 0.f;

    const uint32* Kg = (const uint32*)g_ktb + (size_t)(h * NPOS + split * CHUNK) * 16;
    const uint32* Vg = (const uint32*)g_vtb + (size_t)(h * DHEAD) * (NPOS / 2) + split * (CHUNK / 2);

    int krow_st[4], kcol_st[4], vrow_st[4], vcol_st[4];
#pragma unroll
    for (int it = 0; it < 4; it++) {
        int idx = tid + it * 256;
        krow_st[it] = idx >> 4; kcol_st[it] = idx & 15;
        vrow_st[it] = idx >> 5; vcol_st[it] = idx & 31;
    }

    uint32 pkf[4], pvf[4];
#pragma unroll
    for (int it = 0; it < 4; it++) {
        pkf[it] = Kg[(size_t)krow_st[it] * 16 + kcol_st[it]];
        pvf[it] = Vg[(size_t)vrow_st[it] * (NPOS / 2) + vcol_st[it]];
    }

    for (int tile = 0; tile < NTILES; tile++) {
        __syncthreads();
#pragma unroll
        for (int it = 0; it < 4; it++) {
            sKu[krow_st[it] * 20 + kcol_st[it]] = pkf[it];
            sVu[vrow_st[it] * 36 + vcol_st[it]] = pvf[it];
        }
        __syncthreads();

        if (tile + 1 < NTILES) {
#pragma unroll
            for (int it = 0; it < 4; it++) {
                pkf[it] = Kg[(size_t)((tile + 1) * 64 + krow_st[it]) * 16 + kcol_st[it]];
                pvf[it] = Vg[(size_t)vrow_st[it] * (NPOS / 2) + (tile + 1) * 32 + vcol_st[it]];
            }
        }

        // ---- Phase 1: S MMAs ----
        float sS[4][2][4];
#pragma unroll
        for (int kt = 0; kt < 4; kt++) {
#pragma unroll
            for (int nt = 0; nt < 2; nt++)
#pragma unroll
                for (int c = 0; c < 4; c++) sS[kt][nt][c] = 0.f;
#pragma unroll
            for (int ks = 0; ks < 2; ks++) {
#pragma unroll
                for (int nt = 0; nt < 2; nt++) {
                    int krow = kt * 16 + nt * 8 + g;
                    uint32 b0 = sKu[krow * 20 + tg + 8 * ks];
                    uint32 b1 = sKu[krow * 20 + tg + 4 + 8 * ks];
                    mma16816(sS[kt][nt], qa[ks], b0, b1);
                }
            }
        }

        // ---- Phase 2: one softmax pass ----
        float tm0 = -1e30f, tm1 = -1e30f;
#pragma unroll
        for (int kt = 0; kt < 4; kt++) {
#pragma unroll
            for (int nt = 0; nt < 2; nt++) {
                tm0 = fmaxf(tm0, fmaxf(sS[kt][nt][0], sS[kt][nt][1]));
                tm1 = fmaxf(tm1, fmaxf(sS[kt][nt][2], sS[kt][nt][3]));
            }
        }
        tm0 = fmaxf(tm0, __shfl_xor_sync(0xffffffffu, tm0, 1));
        tm0 = fmaxf(tm0, __shfl_xor_sync(0xffffffffu, tm0, 2));
        tm1 = fmaxf(tm1, __shfl_xor_sync(0xffffffffu, tm1, 1));
        tm1 = fmaxf(tm1, __shfl_xor_sync(0xffffffffu, tm1, 2));
        float nm0 = fmaxf(m0, tm0), nm1 = fmaxf(m1, tm1);
        float c0 = ex2((m0 - nm0) * L2E);
        float c1 = ex2((m1 - nm1) * L2E);
        m0 = nm0; m1 = nm1;
        l0 *= c0; l1 *= c1;
#pragma unroll
        for (int nt = 0; nt < 4; nt++) {
            o[nt][0] *= c0; o[nt][1] *= c0;
            o[nt][2] *= c1; o[nt][3] *= c1;
        }

        // ---- Phase 3: exp + PV MMAs ----
#pragma unroll
        for (int kt = 0; kt < 4; kt++) {
            float p00 = ex2((sS[kt][0][0] - nm0) * L2E);
            float p01 = ex2((sS[kt][0][1] - nm0) * L2E);
            float p10 = ex2((sS[kt][1][0] - nm0) * L2E);
            float p11 = ex2((sS[kt][1][1] - nm0) * L2E);
            float p02 = ex2((sS[kt][0][2] - nm1) * L2E);
            float p03 = ex2((sS[kt][0][3] - nm1) * L2E);
            float p12 = ex2((sS[kt][1][2] - nm1) * L2E);
            float p13 = ex2((sS[kt][1][3] - nm1) * L2E);

            l0 += (p00 + p01) + (p10 + p11);
            l1 += (p02 + p03) + (p12 + p13);

            uint32 pa[4];
            pa[0] = pk2(p00, p01);
            pa[1] = pk2(p02, p03);
            pa[2] = pk2(p10, p11);
            pa[3] = pk2(p12, p13);

#pragma unroll
            for (int nt = 0; nt < 4; nt++) {
                int vrow = nt * 8 + g;
                uint32 b0 = sVu[vrow * 36 + kt * 8 + tg];
                uint32 b1 = sVu[vrow * 36 + kt * 8 + tg + 4];
                mma16816(o[nt], pa, b0, b1);
            }
        }
    }

    l0 += __shfl_xor_sync(0xffffffffu, l0, 1);
    l0 += __shfl_xor_sync(0xffffffffu, l0, 2);
    l1 += __shfl_xor_sync(0xffffffffu, l1, 1);
    l1 += __shfl_xor_sync(0xffffffffu, l1, 2);

    int qg0 = h * NPOS + q0 + g;
    int qg1 = qg0 + 8;
    int pi0 = qg0 * NSPLIT + split;
    int pi1 = qg1 * NSPLIT + split;
    g_pm[pi0] = m0; g_pl[pi0] = l0;
    g_pm[pi1] = m1; g_pl[pi1] = l1;

    float2* P0 = (float2*)(g_pacc + (size_t)pi0 * 32);
    float2* P1 = (float2*)(g_pacc + (size_t)pi1 * 32);
#pragma unroll
    for (int nt = 0; nt < 4; nt++) {
        P0[nt * 4 + tg] = make_float2(o[nt][0], o[nt][1]);
        P1[nt * 4 + tg] = make_float2(o[nt][2], o[nt][3]);
    }
}

// ============================================================
// Kernel 3 (FUSED reduce + outproj): block owns 16 n-positions.
// ============================================================
__global__ void __launch_bounds__(256) fused_out_kernel(
    const float* __restrict__ w, const float* __restrict__ b, float* __restrict__ y)
{
    __shared__ float sO[HID * OPAD];
    int tid = threadIdx.x;
    int n0 = blockIdx.x * 16;

    // ---- Phase A: 64 (h,i) pairs, 4 threads each (8 d's per thread) ----
    {
        int pair = tid >> 2;
        int hh = pair >> 4;
        int il = pair & 15;
        int dq = (tid & 3) * 8;
        int i = n0 + il;
        int base = (hh * NPOS + i) * NSPLIT;

        float pm[NSPLIT], pl[NSPLIT];
#pragma unroll
        for (int s = 0; s < NSPLIT; s++) { pm[s] = g_pm[base + s]; pl[s] = g_pl[base + s]; }
        float M = pm[0];
#pragma unroll
        for (int s = 1; s < NSPLIT; s++) M = fmaxf(M, pm[s]);

        float L = 0.f;
        float num[8];
#pragma unroll
        for (int d = 0; d < 8; d++) num[d] = 0.f;

#pragma unroll
        for (int s = 0; s < NSPLIT; s++) {
            float es = ex2((pm[s] - M) * L2E);
            L += pl[s] * es;
            const float4* pa = (const float4*)(g_pacc + (size_t)(base + s) * 32 + dq);
            float4 a0 = pa[0], a1 = pa[1];
            num[0] += a0.x * es; num[1] += a0.y * es;
            num[2] += a0.z * es; num[3] += a0.w * es;
            num[4] += a1.x * es; num[5] += a1.y * es;
            num[6] += a1.z * es; num[7] += a1.w * es;
        }
        float inv = 1.f / L;
#pragma unroll
        for (int d = 0; d < 8; d++)
            sO[(hh * DHEAD + dq + d) * OPAD + il] = num[d] * inv;
    }
    __syncthreads();

    // ---- Phase B: tf32 MMA ----
    int wp = tid >> 5, lane = tid & 31;
    int g = lane >> 2, tg = lane & 3;
    int ow = wp & 3, nw = wp >> 2;
    int o0 = ow * 16;
    int nl0 = nw * 8;

    float c[4] = {0.f, 0.f, 0.f, 0.f};
    const float* wA0 = w + (size_t)(o0 + g) * HID;
    const float* wA1 = w + (size_t)(o0 + g + 8) * HID;

#pragma unroll
    for (int ks = 0; ks < 16; ks++) {
        int k0 = ks * 8;
        uint32 a[4];
        a[0] = to_tf32(wA0[k0 + tg]);
        a[1] = to_tf32(wA1[k0 + tg]);
        a[2] = to_tf32(wA0[k0 + tg + 4]);
        a[3] = to_tf32(wA1[k0 + tg + 4]);

        uint32 b0 = to_tf32(sO[(k0 + tg) * OPAD + nl0 + g]);
        uint32 b1 = to_tf32(sO[(k0 + tg + 4) * OPAD + nl0 + g]);
        mma1688_tf32(c, a, b0, b1);
    }

    float bb0 = b[o0 + g];
    float bb1 = b[o0 + g + 8];
    int n = n0 + nl0;
    *(float2*)(y + (size_t)(o0 + g) * NPOS + n + 2 * tg)     = make_float2(c[0] + bb0, c[1] + bb0);
    *(float2*)(y + (size_t)(o0 + g + 8) * NPOS + n + 2 * tg) = make_float2(c[2] + bb1, c[3] + bb1);
}

// ============================================================
extern "C" void kernel_launch(void* const* d_in, const int* in_sizes, int n_in,
                              void* d_out, int out_size)
{
    const float* x     = (const float*)d_in[0];
    const float* w_qkv = (const float*)d_in[1];
    const float* w_out = (const float*)d_in[2];
    const float* b_out = (const float*)d_in[3];
    float* y = (float*)d_out;

    qkv_kernel<<<dim3(128, 3), 256>>>(x, w_qkv);
    flash_kernel<<<1024, 256>>>();
    fused_out_kernel<<<256, 256>>>(w_out, b_out, y);
}